// round 3
// baseline (speedup 1.0000x reference)
#include <cuda_runtime.h>
#include <math.h>

// ---------------- problem constants ----------------
#define HID 256          // H
#define NHEAD 4
#define DHEAD 64
#define BATCH 256        // B
#define SEQL 128         // L
#define TT 256           // T
#define TS 255           // T-1 scan steps
#define RROWS (TS*BATCH) // 65280
#define NNODE (BATCH*SEQL) // 32768
#define G3 768           // 3*H

// ---------------- device scratch (static, no allocs) ----------------
__device__ int   g_is64;
__device__ float g_XW[NNODE*HID];            // 33.5MB  nodes @ gat_w
__device__ float g_ASD[NNODE*8];             // a_src(4), a_dst(4) per node
__device__ float g_ROUT[NNODE*HID];          // route_outputs (b,l,h)
__device__ float g_ROUTT[BATCH*HID*SEQL];    // (b,h,l) transposed
__device__ float g_H0[BATCH*HID];            // hidden0
__device__ float g_WIHT[257*G3];             // W_ih^T (k,j)
__device__ float g_WHHT[HID*G3];             // W_hh^T (k,j)
__device__ float g_F1T[512*512];             // fc1_w^T
__device__ float g_GI[RROWS*G3];             // precomputed input gates (200MB)
__device__ float g_HS[RROWS*HID];            // h_t for all steps
__device__ float g_WTD[RROWS*HID];           // weighted context
__device__ float g_RIN[RROWS*512];           // concat(h, weighted)
__device__ float g_FC1[RROWS*512];           // relu(fc1)

// ---------------- small utility kernels ----------------
__global__ void k_detect(const int* __restrict__ t) {
    if (threadIdx.x == 0) {
        int all0 = 1;
        for (int q = 1; q < 256; q += 2) if (t[q] != 0) { all0 = 0; break; }
        g_is64 = all0;   // 1 => trg_id is int64 on disk
    }
}

__global__ void k_memset(float* p, int n) {
    int i = blockIdx.x * blockDim.x + threadIdx.x;
    if (i < n) p[i] = 0.f;
}

// out[c*rows + r] = in[r*cols + c]
__global__ void k_transpose(const float* __restrict__ in, float* __restrict__ out,
                            int rows, int cols) {
    int idx = blockIdx.x * blockDim.x + threadIdx.x;
    if (idx >= rows * cols) return;
    int r = idx / cols, c = idx - r * cols;
    out[c * rows + r] = in[idx];
}

// ---------------- GAT: a_src / a_dst projections ----------------
__global__ void k_asd(const float* __restrict__ asrc, const float* __restrict__ adst) {
    __shared__ float ss[HID], sd[HID];
    int t = threadIdx.x;
    ss[t] = asrc[t]; sd[t] = adst[t];
    __syncthreads();
    int gid = blockIdx.x * 256 + t;
    int n = gid >> 2, h = gid & 3;
    const float* x = &g_XW[n * HID + h * DHEAD];
    const float* cs = &ss[h * DHEAD];
    const float* cd = &sd[h * DHEAD];
    float s = 0.f, d = 0.f;
#pragma unroll 8
    for (int q = 0; q < DHEAD; q++) { float v = x[q]; s += v * cs[q]; d += v * cd[q]; }
    g_ASD[n * 8 + h] = s;
    g_ASD[n * 8 + 4 + h] = d;
}

// ---------------- GAT aggregate + residual + LayerNorm ----------------
__global__ void k_gat(const float* __restrict__ emb, const float* __restrict__ bias,
                      const float* __restrict__ gamma, const float* __restrict__ beta) {
    int i = blockIdx.x;              // node id
    int j = threadIdx.x;             // feature
    int h = j >> 6;                  // head
    int l = i & (SEQL - 1);
    float ad = g_ASD[i * 8 + 4 + h];
    bool v0 = (l > 0), v1 = (l < SEQL - 1);
    float e0 = -1e30f, e1 = -1e30f;
    if (v0) { float e = g_ASD[(i - 1) * 8 + h] + ad; e0 = e > 0.f ? e : 0.2f * e; }
    if (v1) { float e = g_ASD[(i + 1) * 8 + h] + ad; e1 = e > 0.f ? e : 0.2f * e; }
    float emax = fmaxf(e0, e1);
    float x0 = v0 ? expf(e0 - emax) : 0.f;
    float x1 = v1 ? expf(e1 - emax) : 0.f;
    float inv = 1.f / (x0 + x1 + 1e-16f);
    float a0 = x0 * inv, a1 = x1 * inv;
    float val = bias[j] + emb[(long long)i * HID + j];
    if (v0) val += a0 * g_XW[(i - 1) * HID + j];
    if (v1) val += a1 * g_XW[(i + 1) * HID + j];
    // layernorm over 256 features
    __shared__ float red[HID];
    red[j] = val; __syncthreads();
    for (int s = 128; s > 0; s >>= 1) { if (j < s) red[j] += red[j + s]; __syncthreads(); }
    float mean = red[0] * (1.f / HID); __syncthreads();
    float dv = val - mean;
    red[j] = dv * dv; __syncthreads();
    for (int s = 128; s > 0; s >>= 1) { if (j < s) red[j] += red[j + s]; __syncthreads(); }
    float var = red[0] * (1.f / HID);
    g_ROUT[(long long)i * HID + j] = dv * rsqrtf(var + 1e-5f) * gamma[j] + beta[j];
}

__global__ void k_hidden0() {
    int b = blockIdx.x, j = threadIdx.x;
    const float* p = &g_ROUT[(long long)b * SEQL * HID + j];
    float s = 0.f;
    for (int l = 0; l < SEQL; l++) s += p[l * HID];
    g_H0[b * HID + j] = s * (1.f / SEQL);
}

// (b,l,h) -> (b,h,l)
__global__ void k_routt() {
    __shared__ float tile[32][33];
    int b = blockIdx.z;
    int h0 = blockIdx.x * 32, l0 = blockIdx.y * 32;
    int x = threadIdx.x, y = threadIdx.y;
    const float* in = &g_ROUT[(long long)b * SEQL * HID];
    float* out = &g_ROUTT[(long long)b * HID * SEQL];
    for (int yy = y; yy < 32; yy += 8) tile[yy][x] = in[(l0 + yy) * HID + h0 + x];
    __syncthreads();
    for (int yy = y; yy < 32; yy += 8) out[(h0 + yy) * SEQL + l0 + x] = tile[x][yy];
}

// ---------------- generic tiled SGEMM (128x128x8, 8x8/thread) ----------------
// C[m,n] = alpha * sum_k A[m,k]*B[k,n]  (+bias[n]) (+rowScal[m]*rowVec[n]) [relu] [mask->-1e9]
// batching via blockIdx.z with element strides sA,sB,sC. A rows optionally gathered.
__global__ __launch_bounds__(256, 2) void k_sgemm(
    int M, int N, int K,
    const float* __restrict__ A, int lda, long long sA,
    const float* __restrict__ B, int ldb, long long sB,
    float* __restrict__ C, int ldc, long long sC,
    const void* __restrict__ gth,
    const float* __restrict__ rowScal, const float* __restrict__ rowVec,
    const float* __restrict__ bias,
    const int* __restrict__ maskPtr, int maskStride,
    float alpha, int doRelu)
{
    __shared__ float As[8][128];
    __shared__ float Bs[8][128];
    const float* Ab = A + (long long)blockIdx.z * sA;
    const float* Bb = B + (long long)blockIdx.z * sB;
    float* Cb = C + (long long)blockIdx.z * sC;
    int m0 = blockIdx.y * 128, n0 = blockIdx.x * 128;
    int tid = threadIdx.x, tx = tid & 15, ty = tid >> 4;
    float acc[8][8];
#pragma unroll
    for (int i = 0; i < 8; i++)
#pragma unroll
        for (int j = 0; j < 8; j++) acc[i][j] = 0.f;

    int rowL = tid >> 1, kq = (tid & 1) * 4;
    int grow = m0 + rowL; if (grow > M - 1) grow = M - 1;
    const float* Arow;
    if (gth) {
        long long gr = g_is64 ? ((const long long*)gth)[grow]
                              : (long long)((const int*)gth)[grow];
        Arow = Ab + gr * (long long)lda;
    } else {
        Arow = Ab + (long long)grow * lda;
    }
    int kB = tid >> 5, nq = (tid & 31) * 4;

    for (int k0 = 0; k0 < K; k0 += 8) {
        float4 av = *(const float4*)(Arow + k0 + kq);
        As[kq + 0][rowL] = av.x; As[kq + 1][rowL] = av.y;
        As[kq + 2][rowL] = av.z; As[kq + 3][rowL] = av.w;
        *(float4*)&Bs[kB][nq] = *(const float4*)(Bb + (long long)(k0 + kB) * ldb + n0 + nq);
        __syncthreads();
#pragma unroll
        for (int kk = 0; kk < 8; kk++) {
            float a[8], b[8];
            *(float4*)&a[0] = *(const float4*)&As[kk][ty * 4];
            *(float4*)&a[4] = *(const float4*)&As[kk][64 + ty * 4];
            *(float4*)&b[0] = *(const float4*)&Bs[kk][tx * 4];
            *(float4*)&b[4] = *(const float4*)&Bs[kk][64 + tx * 4];
#pragma unroll
            for (int i = 0; i < 8; i++)
#pragma unroll
                for (int j = 0; j < 8; j++) acc[i][j] += a[i] * b[j];
        }
        __syncthreads();
    }
#pragma unroll
    for (int i = 0; i < 8; i++) {
        int mloc = (i < 4) ? ty * 4 + i : 64 + ty * 4 + (i - 4);
        int m = m0 + mloc;
        if (m >= M) continue;
        float rs = rowScal ? rowScal[m] : 0.f;
#pragma unroll
        for (int j = 0; j < 8; j++) {
            int nloc = (j < 4) ? tx * 4 + j : 64 + tx * 4 + (j - 4);
            int n = n0 + nloc;
            float v = acc[i][j] * alpha;
            if (bias)    v += bias[n];
            if (rowScal) v += rs * rowVec[n];
            if (doRelu)  v = fmaxf(v, 0.f);
            if (maskPtr && maskPtr[(long long)blockIdx.z * maskStride + n] == 0) v = -1e9f;
            Cb[(long long)m * ldc + n] = v;
        }
    }
}

// ---------------- one GRU step: gh GEMV + gates (2 batches / block) ----------------
__global__ void k_gru(const float* __restrict__ hprev, const float* __restrict__ gi,
                      const float* __restrict__ whht, const float* __restrict__ bhh,
                      float* __restrict__ hnew)
{
    __shared__ float hsm[HID * 2];   // [k][bb]
    int i = threadIdx.x;             // output feature 0..255
    int b0 = blockIdx.x * 2;
    hsm[2 * i]     = hprev[b0 * HID + i];
    hsm[2 * i + 1] = hprev[(b0 + 1) * HID + i];
    __syncthreads();
    float ar0 = 0.f, az0 = 0.f, an0 = 0.f, ar1 = 0.f, az1 = 0.f, an1 = 0.f;
#pragma unroll 8
    for (int k = 0; k < HID; k++) {
        float2 h2 = *(const float2*)&hsm[2 * k];
        float wr = whht[k * G3 + i];
        float wz = whht[k * G3 + 256 + i];
        float wn = whht[k * G3 + 512 + i];
        ar0 += h2.x * wr; ar1 += h2.y * wr;
        az0 += h2.x * wz; az1 += h2.y * wz;
        an0 += h2.x * wn; an1 += h2.y * wn;
    }
    float br = bhh[i], bz = bhh[256 + i], bn = bhh[512 + i];
#pragma unroll
    for (int bb = 0; bb < 2; bb++) {
        const float* g = gi + (long long)(b0 + bb) * G3;
        float ar = bb ? ar1 : ar0, az = bb ? az1 : az0, an = bb ? an1 : an0;
        float r = 1.f / (1.f + expf(-(g[i] + br + ar)));
        float z = 1.f / (1.f + expf(-(g[256 + i] + bz + az)));
        float n = tanhf(g[512 + i] + r * (bn + an));
        float hp = hsm[2 * i + bb];
        hnew[(long long)(b0 + bb) * HID + i] = (1.f - z) * n + z * hp;
    }
}

// ---------------- softmax over L=128 (one warp per (t,b)) ----------------
__global__ void k_softmax(float* __restrict__ base, const int* __restrict__ mask) {
    int gid = blockIdx.x * blockDim.x + threadIdx.x;
    int w = gid >> 5, lane = gid & 31;
    if (w >= RROWS) return;
    float* row = base + (long long)w * SEQL;
    int b = w & (BATCH - 1);
    float v[4];
#pragma unroll
    for (int q = 0; q < 4; q++) v[q] = row[lane + 32 * q];
    float mx = fmaxf(fmaxf(v[0], v[1]), fmaxf(v[2], v[3]));
    for (int o = 16; o > 0; o >>= 1) mx = fmaxf(mx, __shfl_xor_sync(0xffffffffu, mx, o));
    float s = 0.f;
#pragma unroll
    for (int q = 0; q < 4; q++) { v[q] = expf(v[q] - mx); s += v[q]; }
    for (int o = 16; o > 0; o >>= 1) s += __shfl_xor_sync(0xffffffffu, s, o);
    float inv = 1.f / s;
    const int* mk = mask + b * SEQL;
#pragma unroll
    for (int q = 0; q < 4; q++) {
        int l = lane + 32 * q;
        float a = v[q] * inv;
        row[l] = mk[l] ? a : 0.f;
    }
}

// ---------------- concat(h, weighted) -> RIN ----------------
__global__ void k_concat() {
    long long idx = (long long)blockIdx.x * blockDim.x + threadIdx.x;
    if (idx >= (long long)RROWS * 512) return;
    int r = (int)(idx >> 9), j = (int)(idx & 511);
    g_RIN[idx] = (j < 256) ? g_HS[(long long)r * HID + j]
                           : g_WTD[(long long)r * HID + (j - 256)];
}

// ---------------- fc2 + sigmoid (one warp per row) ----------------
__global__ void k_fc2(const float* __restrict__ w2, const float* __restrict__ b2,
                      float* __restrict__ outr) {
    int gid = blockIdx.x * blockDim.x + threadIdx.x;
    int w = gid >> 5, lane = gid & 31;
    if (w >= RROWS) return;
    const float* row = &g_FC1[(long long)w * 512];
    float s = 0.f;
#pragma unroll
    for (int q = 0; q < 16; q++) s += row[lane + 32 * q] * w2[lane + 32 * q];
    for (int o = 16; o > 0; o >>= 1) s += __shfl_xor_sync(0xffffffffu, s, o);
    if (lane == 0) outr[w] = 1.f / (1.f + expf(-(s + b2[0])));
}

// ---------------- host launcher ----------------
extern "C" void kernel_launch(void* const* d_in, const int* in_sizes, int n_in,
                              void* d_out, int out_size) {
    const float* route_emb = (const float*)d_in[0];
    const int*   trg_id    = (const int*)  d_in[2];   // int32 or int64 (auto-detected)
    const float* trg_rate  = (const float*)d_in[3];
    const int*   mask      = (const int*)  d_in[5];
    const float* emb_id    = (const float*)d_in[6];
    const float* gat_w     = (const float*)d_in[7];
    const float* a_src     = (const float*)d_in[8];
    const float* a_dst     = (const float*)d_in[9];
    const float* gat_bias  = (const float*)d_in[10];
    const float* ln_g      = (const float*)d_in[11];
    const float* ln_b      = (const float*)d_in[12];
    const float* w_ih      = (const float*)d_in[13];
    const float* w_hh      = (const float*)d_in[14];
    const float* b_ih      = (const float*)d_in[15];
    const float* b_hh      = (const float*)d_in[16];
    const float* fc1w      = (const float*)d_in[17];
    const float* fc1b      = (const float*)d_in[18];
    const float* fc2w      = (const float*)d_in[19];
    const float* fc2b      = (const float*)d_in[20];
    float* out = (float*)d_out;

    float *XW, *ROUT, *ROUTT, *H0, *WIHT, *WHHT, *F1T, *GI, *HS, *WTD, *RIN, *FC1;
    cudaGetSymbolAddress((void**)&XW,   g_XW);
    cudaGetSymbolAddress((void**)&ROUT, g_ROUT);
    cudaGetSymbolAddress((void**)&ROUTT,g_ROUTT);
    cudaGetSymbolAddress((void**)&H0,   g_H0);
    cudaGetSymbolAddress((void**)&WIHT, g_WIHT);
    cudaGetSymbolAddress((void**)&WHHT, g_WHHT);
    cudaGetSymbolAddress((void**)&F1T,  g_F1T);
    cudaGetSymbolAddress((void**)&GI,   g_GI);
    cudaGetSymbolAddress((void**)&HS,   g_HS);
    cudaGetSymbolAddress((void**)&WTD,  g_WTD);
    cudaGetSymbolAddress((void**)&RIN,  g_RIN);
    cudaGetSymbolAddress((void**)&FC1,  g_FC1);

    const long long IDSZ = (long long)TT * BATCH * SEQL;   // 8388608

    // dtype sniff for trg_id + zero the t=0 output rows
    k_detect<<<1, 32>>>(trg_id);
    k_memset<<<(BATCH * SEQL + 255) / 256, 256>>>(out, BATCH * SEQL);
    k_memset<<<1, 256>>>(out + IDSZ, BATCH);

    // weight transposes
    k_transpose<<<(768 * 257 + 255) / 256, 256>>>(w_ih, WIHT, 768, 257);
    k_transpose<<<(768 * 256 + 255) / 256, 256>>>(w_hh, WHHT, 768, 256);
    k_transpose<<<(512 * 512 + 255) / 256, 256>>>(fc1w, F1T, 512, 512);

    // --- GAT ---
    // XW = nodes @ gat_w   (32768 x 256 x 256)
    k_sgemm<<<dim3(2, 256, 1), 256>>>(NNODE, HID, HID,
        route_emb, HID, 0, gat_w, HID, 0, XW, HID, 0,
        nullptr, nullptr, nullptr, nullptr, nullptr, 0, 1.f, 0);
    k_asd<<<NNODE * 4 / 256, 256>>>(a_src, a_dst);
    k_gat<<<NNODE, HID>>>(route_emb, gat_bias, ln_g, ln_b);
    k_hidden0<<<BATCH, HID>>>();
    k_routt<<<dim3(8, 4, BATCH), dim3(32, 8)>>>();

    // --- GI = gather(emb_id) @ W_ih[:, :256]^T + rate*W_ih[:,256] + b_ih ---
    k_sgemm<<<dim3(6, 510, 1), 256>>>(RROWS, G3, HID,
        emb_id, HID, 0, WIHT, G3, 0, GI, G3, 0,
        (const void*)trg_id, trg_rate, WIHT + 256 * G3, b_ih,
        nullptr, 0, 1.f, 0);

    // --- sequential GRU scan (only gh on critical path) ---
    for (int t = 0; t < TS; t++) {
        const float* hp = t ? HS + (long long)(t - 1) * BATCH * HID : H0;
        k_gru<<<BATCH / 2, HID>>>(hp, GI + (long long)t * BATCH * G3, WHHT, b_hh,
                                  HS + (long long)t * BATCH * HID);
    }

    // --- scores: S[t,b,l] = (1/16) * HS[t,b,:]·ROUT[b,l,:]  -> d_out (pre-softmax) ---
    k_sgemm<<<dim3(1, 2, BATCH), 256>>>(TS, SEQL, HID,
        HS, BATCH * HID, HID,                 // A: (t,k) per batch b
        ROUTT, SEQL, (long long)HID * SEQL,   // B: (k=h, n=l) per batch b
        out + (long long)BATCH * SEQL, BATCH * SEQL, SEQL,   // C at (t+1,b,l)
        nullptr, nullptr, nullptr, nullptr,
        mask, SEQL, 0.0625f, 0);

    // --- softmax over l, masked zeros, in place in d_out ---
    k_softmax<<<RROWS / 4, 128>>>(out + (long long)BATCH * SEQL, mask);

    // --- weighted[t,b,h] = attn[t,b,:] @ ROUT[b,:,h] ---
    k_sgemm<<<dim3(2, 2, BATCH), 256>>>(TS, HID, SEQL,
        out + (long long)BATCH * SEQL, BATCH * SEQL, SEQL,   // A: attn (t,l) per b
        ROUT, HID, (long long)SEQL * HID,                    // B: (k=l, n=h) per b
        WTD, BATCH * HID, HID,                               // C: (t,b,h)
        nullptr, nullptr, nullptr, nullptr, nullptr, 0, 1.f, 0);

    // --- rate head: fc1 (relu) then fc2 (sigmoid) ---
    k_concat<<<(int)(((long long)RROWS * 512 + 255) / 256), 256>>>();
    k_sgemm<<<dim3(4, 510, 1), 256>>>(RROWS, 512, 512,
        RIN, 512, 0, F1T, 512, 0, FC1, 512, 0,
        nullptr, nullptr, nullptr, fc1b, nullptr, 0, 1.f, 1);
    k_fc2<<<(RROWS * 32 + 255) / 256, 256>>>(fc2w, fc2b, out + IDSZ + BATCH);
}